// round 14
// baseline (speedup 1.0000x reference)
#include <cuda_runtime.h>
#include <cuda_fp16.h>
#include <math.h>
#include <stdint.h>

#define T_TOK   16384
#define D_EMB   768
#define D_HID   3072
#define N_HEAD  12
#define HD      64
#define N_SEQ   1024
#define N_BATCH 16
#define GEMM_GRID 296

// ---------------- scratch (device globals: allocation-free) ----------------
__device__ __half g_xn [T_TOK * D_EMB];
__device__ __half g_qkv[T_TOK * 3 * D_EMB];
__device__ __half g_ctx[T_TOK * D_EMB];
__device__ __half g_x1 [T_TOK * D_EMB];
__device__ __half g_h  [T_TOK * D_HID];
__device__ __half g_wq[3 * D_EMB * D_EMB];
__device__ __half g_wp[D_EMB * D_EMB];
__device__ __half g_w1[D_HID * D_EMB];
__device__ __half g_w2[D_EMB * D_HID];

// ---------------- helpers ----------------
__device__ __forceinline__ uint32_t s2u(const void* p) {
    uint32_t a;
    asm("{ .reg .u64 t; cvta.to.shared.u64 t, %1; cvt.u32.u64 %0, t; }" : "=r"(a) : "l"(p));
    return a;
}
__device__ __forceinline__ void cp_async16(uint32_t dst, const void* src) {
    asm volatile("cp.async.cg.shared.global [%0], [%1], 16;" :: "r"(dst), "l"(src) : "memory");
}
#define CP_COMMIT() asm volatile("cp.async.commit_group;" ::: "memory")
#define CP_WAIT(n)  asm volatile("cp.async.wait_group %0;" :: "n"(n) : "memory")

__device__ __forceinline__ uint32_t lds32(uint32_t addr) {
    uint32_t v;
    asm volatile("ld.shared.b32 %0, [%1];" : "=r"(v) : "r"(addr));
    return v;
}
__device__ __forceinline__ void ldsm_x4(uint32_t* r, uint32_t addr) {
    asm volatile("ldmatrix.sync.aligned.m8n8.x4.shared.b16 {%0,%1,%2,%3}, [%4];"
                 : "=r"(r[0]), "=r"(r[1]), "=r"(r[2]), "=r"(r[3]) : "r"(addr));
}
__device__ __forceinline__ void ldsm_x4_t(uint32_t* r, uint32_t addr) {
    asm volatile("ldmatrix.sync.aligned.m8n8.x4.trans.shared.b16 {%0,%1,%2,%3}, [%4];"
                 : "=r"(r[0]), "=r"(r[1]), "=r"(r[2]), "=r"(r[3]) : "r"(addr));
}

// D += A * B  (m16n8k16 fp16, fp32 accum)
__device__ __forceinline__ void mma_f16(float* d, const uint32_t* a, const uint32_t* b) {
    asm volatile(
        "mma.sync.aligned.m16n8k16.row.col.f32.f16.f16.f32 "
        "{%0,%1,%2,%3}, {%4,%5,%6,%7}, {%8,%9}, {%0,%1,%2,%3};"
        : "+f"(d[0]), "+f"(d[1]), "+f"(d[2]), "+f"(d[3])
        : "r"(a[0]), "r"(a[1]), "r"(a[2]), "r"(a[3]), "r"(b[0]), "r"(b[1]));
}
__device__ __forceinline__ uint32_t h2u(float a, float b) {
    __half2 h = __floats2half2_rn(a, b);
    return *(uint32_t*)&h;
}

// ---------------- fused prep: LN1 (warp/row) + weight conversion -----------
#define LN_BLOCKS (T_TOK / 8)
#define WQ4 442368
#define WP4 147456
#define W14 589824
#define W24 589824
#define PREP_BLOCKS ((WQ4 + WP4 + W14 + W24) / 256)
__global__ __launch_bounds__(256) void prep_ln1_kernel(
    const float* __restrict__ x, const float* __restrict__ lg,
    const float* __restrict__ lb, __half* __restrict__ xn,
    const float4* __restrict__ wq, const float4* __restrict__ wp,
    const float4* __restrict__ w1, const float4* __restrict__ w2,
    __half2* __restrict__ oq, __half2* __restrict__ op,
    __half2* __restrict__ o1, __half2* __restrict__ o2)
{
    const int tid = threadIdx.x;
    if (blockIdx.x < LN_BLOCKS) {
        const int row = blockIdx.x * 8 + (tid >> 5);
        const int lane = tid & 31;
        const float4* xr = (const float4*)(x + (size_t)row * D_EMB);
        float4 v[6];
        float s = 0.f, q = 0.f;
        #pragma unroll
        for (int u = 0; u < 6; u++) {
            v[u] = xr[lane + u * 32];
            s += v[u].x + v[u].y + v[u].z + v[u].w;
            q += v[u].x * v[u].x + v[u].y * v[u].y + v[u].z * v[u].z + v[u].w * v[u].w;
        }
        #pragma unroll
        for (int o = 16; o > 0; o >>= 1) {
            s += __shfl_xor_sync(0xffffffffu, s, o);
            q += __shfl_xor_sync(0xffffffffu, q, o);
        }
        const float mu = s * (1.0f / D_EMB);
        const float rstd = rsqrtf(q * (1.0f / D_EMB) - mu * mu + 1e-6f);
        const float4* gr = (const float4*)lg;
        const float4* br = (const float4*)lb;
        uint2* orow = (uint2*)(xn + (size_t)row * D_EMB);
        #pragma unroll
        for (int u = 0; u < 6; u++) {
            const int c4 = lane + u * 32;
            float4 g4 = gr[c4], b4 = br[c4];
            float y0 = (v[u].x - mu) * rstd * g4.x + b4.x;
            float y1 = (v[u].y - mu) * rstd * g4.y + b4.y;
            float y2 = (v[u].z - mu) * rstd * g4.z + b4.z;
            float y3 = (v[u].w - mu) * rstd * g4.w + b4.w;
            orow[c4] = make_uint2(h2u(y0, y1), h2u(y2, y3));
        }
        return;
    }
    int i = (blockIdx.x - LN_BLOCKS) * 256 + tid;
    const float4* src; __half2* dst; int r;
    if (i < WQ4) { src = wq; dst = oq; r = i; }
    else if (i < WQ4 + WP4) { src = wp; dst = op; r = i - WQ4; }
    else if (i < WQ4 + WP4 + W14) { src = w1; dst = o1; r = i - WQ4 - WP4; }
    else { src = w2; dst = o2; r = i - WQ4 - WP4 - W14; }
    float4 v = src[r];
    dst[2 * r]     = __floats2half2_rn(v.x, v.y);
    dst[2 * r + 1] = __floats2half2_rn(v.z, v.w);
}

// ---------------- LN2: warp per row, fp16 in, fp16 out ---------------------
__global__ __launch_bounds__(256) void ln_h_kernel(
    const __half* __restrict__ x, const float* __restrict__ lg,
    const float* __restrict__ lb, __half* __restrict__ out)
{
    const int row = blockIdx.x * 8 + (threadIdx.x >> 5);
    const int lane = threadIdx.x & 31;
    const uint4* xr = (const uint4*)(x + (size_t)row * D_EMB);
    uint4 raw[3];
    float vals[3][8];
    float s = 0.f, q = 0.f;
    #pragma unroll
    for (int u = 0; u < 3; u++) {
        raw[u] = xr[lane + u * 32];
        const uint32_t* w = (const uint32_t*)&raw[u];
        #pragma unroll
        for (int p = 0; p < 4; p++) {
            float2 f = __half22float2(*(const __half2*)&w[p]);
            vals[u][2 * p] = f.x; vals[u][2 * p + 1] = f.y;
            s += f.x + f.y;
            q += f.x * f.x + f.y * f.y;
        }
    }
    #pragma unroll
    for (int o = 16; o > 0; o >>= 1) {
        s += __shfl_xor_sync(0xffffffffu, s, o);
        q += __shfl_xor_sync(0xffffffffu, q, o);
    }
    const float mu = s * (1.0f / D_EMB);
    const float rstd = rsqrtf(q * (1.0f / D_EMB) - mu * mu + 1e-6f);
    uint4* orow = (uint4*)(out + (size_t)row * D_EMB);
    const float4* gr = (const float4*)lg;
    const float4* br = (const float4*)lb;
    #pragma unroll
    for (int u = 0; u < 3; u++) {
        const int c8 = lane + u * 32;
        float4 g0 = gr[2 * c8], g1 = gr[2 * c8 + 1];
        float4 b0 = br[2 * c8], b1 = br[2 * c8 + 1];
        uint4 o4;
        o4.x = h2u((vals[u][0] - mu) * rstd * g0.x + b0.x, (vals[u][1] - mu) * rstd * g0.y + b0.y);
        o4.y = h2u((vals[u][2] - mu) * rstd * g0.z + b0.z, (vals[u][3] - mu) * rstd * g0.w + b0.w);
        o4.z = h2u((vals[u][4] - mu) * rstd * g1.x + b1.x, (vals[u][5] - mu) * rstd * g1.y + b1.y);
        o4.w = h2u((vals[u][6] - mu) * rstd * g1.z + b1.z, (vals[u][7] - mu) * rstd * g1.w + b1.w);
        orow[c8] = o4;
    }
}

// ---------------- persistent fp16 mma GEMM with cross-tile prefetch --------
// MODE 0: +bias -> half      MODE 2: gelu(+bias) -> half
// MODE 3: +bias + f32 res -> half     MODE 4: +bias + half res -> f32
#define TILE_BYTES  16384u
#define STAGE_BYTES 32768u
template <int MODE>
__global__ __launch_bounds__(256, 2) void mma_gemm_h(
    const __half* __restrict__ A, const __half* __restrict__ B,
    const float* __restrict__ bias, const void* __restrict__ res,
    void* __restrict__ Cout, int M, int N, int K)
{
    extern __shared__ char smc[];
    const uint32_t sbase = s2u(smc);
    const int tid = threadIdx.x, wid = tid >> 5, lane = tid & 31;
    const int g = lane >> 2, t = lane & 3;
    const int wm = wid >> 2, wn = wid & 3;
    const int NC = K >> 6;                 // even for K=768 (12) and K=3072 (48)
    const int nx = N >> 7;
    const int ntiles = nx * (M >> 7);

    const uint32_t lx = (uint32_t)(lane & 7);
    uint32_t aRow[4];
    #pragma unroll
    for (int i = 0; i < 4; i++)
        aRow[i] = (uint32_t)((wm * 64 + i * 16 + ((lane >> 3) & 1) * 8 + (lane & 7)) * 128);
    uint32_t coA[4], coB[4];
    #pragma unroll
    for (int ks = 0; ks < 4; ks++) {
        coA[ks] = (((uint32_t)(2 * ks) + (uint32_t)(lane >> 4)) ^ lx) << 4;
        coB[ks] = (((uint32_t)(2 * ks) + (uint32_t)((lane >> 3) & 1)) ^ lx) << 4;
    }
    uint32_t bRow[2];
    #pragma unroll
    for (int p = 0; p < 2; p++)
        bRow[p] = (uint32_t)((wn * 32 + 16 * p + (lane >> 4) * 8 + (lane & 7)) * 128);

    // load one 128x64 A chunk + 128x64 B chunk into stage s
    auto load_chunk = [&](const __half* Ap, const __half* Bp, int s) {
        uint32_t sa = sbase + (uint32_t)s * STAGE_BYTES;
        uint32_t sb = sa + TILE_BYTES;
        #pragma unroll
        for (int q = 0; q < 4; q++) {
            int it = tid + q * 256;
            int r = it >> 3, c = it & 7;
            uint32_t off = (uint32_t)(r * 128) + (((uint32_t)c ^ (uint32_t)(r & 7)) << 4);
            cp_async16(sa + off, Ap + (size_t)r * K + c * 8);
            cp_async16(sb + off, Bp + (size_t)r * K + c * 8);
        }
        CP_COMMIT();
    };

    int tile = blockIdx.x;
    if (tile < ntiles)
        load_chunk(A + (size_t)((tile / nx) * 128) * K,
                   B + (size_t)((tile % nx) * 128) * K, 0);

    for (; tile < ntiles; tile += GEMM_GRID) {
        const int m0 = (tile / nx) * 128, n0 = (tile % nx) * 128;
        const __half* Agb = A + (size_t)m0 * K;
        const __half* Bgb = B + (size_t)n0 * K;
        const int ntile = tile + GEMM_GRID;

        float acc[4][4][4];
        #pragma unroll
        for (int i = 0; i < 4; i++)
            #pragma unroll
            for (int j = 0; j < 4; j++)
                #pragma unroll
                for (int q = 0; q < 4; q++) acc[i][j][q] = 0.f;

        for (int c = 0; c < NC; c++) {
            const int cur = c & 1;
            CP_WAIT(0);
            __syncthreads();
            if (c + 1 < NC) {
                load_chunk(Agb + (size_t)(c + 1) * 64, Bgb + (size_t)(c + 1) * 64, cur ^ 1);
            } else if (ntile < ntiles) {
                // cross-tile prefetch: next tile's chunk 0 into the freed buffer
                // (NC even -> cur^1 == 0, matching next tile's first iteration)
                load_chunk(A + (size_t)((ntile / nx) * 128) * K,
                           B + (size_t)((ntile % nx) * 128) * K, cur ^ 1);
            }

            const uint32_t ab = sbase + (uint32_t)cur * STAGE_BYTES;
            const uint32_t bb = ab + TILE_BYTES;

            #pragma unroll
            for (int ks = 0; ks < 4; ks++) {
                uint32_t afr[4][4];
                #pragma unroll
                for (int i = 0; i < 4; i++)
                    ldsm_x4(afr[i], ab + aRow[i] + coA[ks]);
                uint32_t bq[2][4];
                ldsm_x4(bq[0], bb + bRow[0] + coB[ks]);
                ldsm_x4(bq[1], bb + bRow[1] + coB[ks]);
                #pragma unroll
                for (int i = 0; i < 4; i++) {
                    #pragma unroll
                    for (int j = 0; j < 4; j++)
                        mma_f16(acc[i][j], afr[i], &bq[j >> 1][(j & 1) * 2]);
                }
            }
        }

        // epilogue (no smem use: overlaps with prefetch in flight)
        #pragma unroll
        for (int i = 0; i < 4; i++) {
            const int r0 = m0 + wm * 64 + i * 16 + g;
            #pragma unroll
            for (int j = 0; j < 4; j++) {
                const int cc = n0 + wn * 32 + j * 8 + 2 * t;
                float2 bv = *(const float2*)(bias + cc);
                float v00 = acc[i][j][0] + bv.x, v01 = acc[i][j][1] + bv.y;
                float v10 = acc[i][j][2] + bv.x, v11 = acc[i][j][3] + bv.y;
                if (MODE == 3) {
                    const float* rf = (const float*)res;
                    float2 r0v = *(const float2*)(rf + (size_t)r0 * N + cc);
                    float2 r1v = *(const float2*)(rf + (size_t)(r0 + 8) * N + cc);
                    v00 += r0v.x; v01 += r0v.y; v10 += r1v.x; v11 += r1v.y;
                }
                if (MODE == 4) {
                    const __half* rh = (const __half*)res;
                    float2 r0v = __half22float2(*(const __half2*)(rh + (size_t)r0 * N + cc));
                    float2 r1v = __half22float2(*(const __half2*)(rh + (size_t)(r0 + 8) * N + cc));
                    v00 += r0v.x; v01 += r0v.y; v10 += r1v.x; v11 += r1v.y;
                }
                if (MODE == 2) {
                    v00 = 0.5f * v00 * (1.0f + erff(v00 * 0.70710678118654752f));
                    v01 = 0.5f * v01 * (1.0f + erff(v01 * 0.70710678118654752f));
                    v10 = 0.5f * v10 * (1.0f + erff(v10 * 0.70710678118654752f));
                    v11 = 0.5f * v11 * (1.0f + erff(v11 * 0.70710678118654752f));
                }
                if (MODE == 4) {
                    float* Cf = (float*)Cout;
                    *(float2*)(Cf + (size_t)r0 * N + cc)       = make_float2(v00, v01);
                    *(float2*)(Cf + (size_t)(r0 + 8) * N + cc) = make_float2(v10, v11);
                } else {
                    __half* Ch = (__half*)Cout;
                    *(__half2*)(Ch + (size_t)r0 * N + cc)       = __floats2half2_rn(v00, v01);
                    *(__half2*)(Ch + (size_t)(r0 + 8) * N + cc) = __floats2half2_rn(v10, v11);
                }
            }
        }
    }
}

// ---------------- Flash attention: exp2-folded softmax (R13 version) ------
__global__ __launch_bounds__(256) void attn_mma_kernel(
    const __half* __restrict__ qkv, __half* __restrict__ ctx)
{
    __shared__ __align__(16) char sQ[16384];
    __shared__ __align__(16) char sK[2][8192];
    __shared__ __align__(16) char sV[2][8192];

    const int tid = threadIdx.x, wid = tid >> 5, lane = tid & 31;
    const int g = lane >> 2, t = lane & 3;
    const int bh = blockIdx.y, b = bh / N_HEAD, h = bh % N_HEAD;
    const int q0 = blockIdx.x * 128;
    const size_t tok_base = (size_t)b * N_SEQ;
    const int hoff = h * HD;
    const uint32_t uQ = s2u(sQ);

    #pragma unroll
    for (int qi = 0; qi < 4; qi++) {
        int it = tid + qi * 256, r = it >> 3, c = it & 7;
        cp_async16(uQ + (uint32_t)(r * 128 + ((c ^ (r & 7)) * 16)),
                   qkv + (tok_base + q0 + r) * 2304 + hoff + c * 8);
    }
    {
        uint32_t uK0 = s2u(sK[0]), uV0 = s2u(sV[0]);
        #pragma unroll
        for (int qi = 0; qi < 2; qi++) {
            int it = tid + qi * 256, r = it >> 3, c = it & 7;
            uint32_t off = (uint32_t)(r * 128 + ((c ^ (r & 7)) * 16));
            cp_async16(uK0 + off, qkv + (tok_base + r) * 2304 + D_EMB + hoff + c * 8);
            cp_async16(uV0 + off, qkv + (tok_base + r) * 2304 + 2 * D_EMB + hoff + c * 8);
        }
    }
    CP_COMMIT();
    CP_WAIT(0);
    __syncthreads();

    uint32_t qf[4][4];
    {
        const int rq = wid * 16 + g;
        const __half2 s8 = __floats2half2_rn(0.18033688f, 0.18033688f);
        #pragma unroll
        for (int ks = 0; ks < 4; ks++) {
            uint32_t ca = (uint32_t)(((2 * ks) ^ (rq & 7)) * 16 + t * 4);
            uint32_t cb = (uint32_t)(((2 * ks + 1) ^ (rq & 7)) * 16 + t * 4);
            qf[ks][0] = lds32(uQ + rq * 128 + ca);
            qf[ks][1] = lds32(uQ + (rq + 8) * 128 + ca);
            qf[ks][2] = lds32(uQ + rq * 128 + cb);
            qf[ks][3] = lds32(uQ + (rq + 8) * 128 + cb);
            #pragma unroll
            for (int u = 0; u < 4; u++) {
                __half2 hv = *(__half2*)&qf[ks][u];
                hv = __hmul2(hv, s8);
                qf[ks][u] = *(uint32_t*)&hv;
            }
        }
    }

    const uint32_t lx = (uint32_t)(lane & 7);
    uint32_t kRow[4], coB[4];
    #pragma unroll
    for (int p = 0; p < 4; p++)
        kRow[p] = (uint32_t)((16 * p + (lane >> 4) * 8 + (lane & 7)) * 128);
    #pragma unroll
    for (int ks = 0; ks < 4; ks++)
        coB[ks] = (((uint32_t)(2 * ks) + (uint32_t)((lane >> 3) & 1)) ^ lx) << 4;
    const uint32_t vRow = (uint32_t)(((lane & 7) + ((lane >> 3) & 1) * 8) * 128);
    uint32_t coV[4];
    #pragma unroll
    for (int jp = 0; jp < 4; jp++)
        coV[jp] = (((uint32_t)(2 * jp) + (uint32_t)(lane >> 4)) ^ lx) << 4;

    float m_g = -1e30f, m_g8 = -1e30f, l_g = 0.f, l_g8 = 0.f;
    float of[8][4];
    #pragma unroll
    for (int j = 0; j < 8; j++)
        #pragma unroll
        for (int q = 0; q < 4; q++) of[j][q] = 0.f;

    for (int kt = 0; kt < N_SEQ / 64; kt++) {
        CP_WAIT(0);
        __syncthreads();

        if (kt + 1 < N_SEQ / 64) {
            uint32_t uKn = s2u(sK[(kt + 1) & 1]), uVn = s2u(sV[(kt + 1) & 1]);
            #pragma unroll
            for (int qi = 0; qi < 2; qi++) {
                int it = tid + qi * 256, r = it >> 3, c = it & 7;
                uint32_t off = (uint32_t)(r * 128 + ((c ^ (r & 7)) * 16));
                cp_async16(uKn + off, qkv + (tok_base + (kt + 1) * 64 + r) * 2304 + D_EMB + hoff + c * 8);
                cp_async16(uVn + off, qkv + (tok_base + (kt + 1) * 64 + r) * 2304 + 2 * D_EMB + hoff + c * 8);
            }
            CP_COMMIT();
        }

        const uint32_t uKb = s2u(sK[kt & 1]);
        float sf[8][4];
        #pragma unroll
        for (int j = 0; j < 8; j++) {
            sf[j][0] = 0.f; sf[j][1] = 0.f; sf[j][2] = 0.f; sf[j][3] = 0.f;
        }
        #pragma unroll
        for (int ks = 0; ks < 4; ks++) {
            uint32_t kq[4][4];
            #pragma unroll
            for (int p = 0; p < 4; p++)
                ldsm_x4(kq[p], uKb + kRow[p] + coB[ks]);
            #pragma unroll
            for (int j = 0; j < 8; j++)
                mma_f16(sf[j], qf[ks], &kq[j >> 1][(j & 1) * 2]);
        }

        float mg = m_g, mg8 = m_g8;
        #pragma unroll
        for (int j = 0; j < 8; j++) {
            mg  = fmaxf(mg,  fmaxf(sf[j][0], sf[j][1]));
            mg8 = fmaxf(mg8, fmaxf(sf[j][2], sf[j][3]));
        }
        mg  = fmaxf(mg,  __shfl_xor_sync(0xffffffffu, mg, 1));
        mg  = fmaxf(mg,  __shfl_xor_sync(0xffffffffu, mg, 2));
        mg8 = fmaxf(mg8, __shfl_xor_sync(0xffffffffu, mg8, 1));
        mg8 = fmaxf(mg8, __shfl_xor_sync(0xffffffffu, mg8, 2));
        const float alpha_g = exp2f(m_g - mg), alpha_g8 = exp2f(m_g8 - mg8);
        m_g = mg; m_g8 = mg8;

        float sl_g = 0.f, sl_g8 = 0.f;
        #pragma unroll
        for (int j = 0; j < 8; j++) {
            sf[j][0] = exp2f(sf[j][0] - mg);
            sf[j][1] = exp2f(sf[j][1] - mg);
            sf[j][2] = exp2f(sf[j][2] - mg8);
            sf[j][3] = exp2f(sf[j][3] - mg8);
            sl_g  += sf[j][0] + sf[j][1];
            sl_g8 += sf[j][2] + sf[j][3];
        }
        sl_g  += __shfl_xor_sync(0xffffffffu, sl_g, 1);
        sl_g  += __shfl_xor_sync(0xffffffffu, sl_g, 2);
        sl_g8 += __shfl_xor_sync(0xffffffffu, sl_g8, 1);
        sl_g8 += __shfl_xor_sync(0xffffffffu, sl_g8, 2);
        l_g  = l_g  * alpha_g  + sl_g;
        l_g8 = l_g8 * alpha_g8 + sl_g8;

        uint32_t pf[4][4];
        #pragma unroll
        for (int kp = 0; kp < 4; kp++) {
            pf[kp][0] = h2u(sf[2 * kp][0],     sf[2 * kp][1]);
            pf[kp][1] = h2u(sf[2 * kp][2],     sf[2 * kp][3]);
            pf[kp][2] = h2u(sf[2 * kp + 1][0], sf[2 * kp + 1][1]);
            pf[kp][3] = h2u(sf[2 * kp + 1][2], sf[2 * kp + 1][3]);
        }

        #pragma unroll
        for (int jd = 0; jd < 8; jd++) {
            of[jd][0] *= alpha_g;  of[jd][1] *= alpha_g;
            of[jd][2] *= alpha_g8; of[jd][3] *= alpha_g8;
        }
        const uint32_t uVb = s2u(sV[kt & 1]);
        #pragma unroll
        for (int kp = 0; kp < 4; kp++) {
            uint32_t vqf[4][4];
            #pragma unroll
            for (int jp = 0; jp < 4; jp++)
                ldsm_x4_t(vqf[jp], uVb + (uint32_t)(kp * 2048) + vRow + coV[jp]);
            #pragma unroll
            for (int jd = 0; jd < 8; jd++)
                mma_f16(of[jd], pf[kp], &vqf[jd >> 1][(jd & 1) * 2]);
        }
    }

    const float il_g = 1.0f / l_g, il_g8 = 1.0f / l_g8;
    const int rq = wid * 16 + g;
    #pragma unroll
    for (int jd = 0; jd < 8; jd++) {
        const int col = hoff + 8 * jd + 2 * t;
        *(__half2*)(ctx + (tok_base + q0 + rq) * D_EMB + col) =
            __floats2half2_rn(of[jd][0] * il_g, of[jd][1] * il_g);
        *(__half2*)(ctx + (tok_base + q0 + rq + 8) * D_EMB + col) =
            __floats2half2_rn(of[jd][2] * il_g8, of[jd][3] * il_g8);
    }
}

// ---------------- host launcher ----------------
extern "C" void kernel_launch(void* const* d_in, const int* in_sizes, int n_in,
                              void* d_out, int out_size)
{
    const float* x      = (const float*)d_in[0];
    const float* ln1_g  = (const float*)d_in[1];
    const float* ln1_b  = (const float*)d_in[2];
    const float* qkv_w  = (const float*)d_in[3];
    const float* qkv_b  = (const float*)d_in[4];
    const float* proj_w = (const float*)d_in[5];
    const float* proj_b = (const float*)d_in[6];
    const float* ln2_g  = (const float*)d_in[7];
    const float* ln2_b  = (const float*)d_in[8];
    const float* fc1_w  = (const float*)d_in[9];
    const float* fc1_b  = (const float*)d_in[10];
    const float* fc2_w  = (const float*)d_in[11];
    const float* fc2_b  = (const float*)d_in[12];
    float* out = (float*)d_out;

    __half *p_xn, *p_qkv, *p_ctx, *p_x1, *p_h, *p_wq, *p_wp, *p_w1, *p_w2;
    cudaGetSymbolAddress((void**)&p_xn,  g_xn);
    cudaGetSymbolAddress((void**)&p_qkv, g_qkv);
    cudaGetSymbolAddress((void**)&p_ctx, g_ctx);
    cudaGetSymbolAddress((void**)&p_x1,  g_x1);
    cudaGetSymbolAddress((void**)&p_h,   g_h);
    cudaGetSymbolAddress((void**)&p_wq,  g_wq);
    cudaGetSymbolAddress((void**)&p_wp,  g_wp);
    cudaGetSymbolAddress((void**)&p_w1,  g_w1);
    cudaGetSymbolAddress((void**)&p_w2,  g_w2);

    const int gemm_smem = 2 * (int)STAGE_BYTES;   // 65536 B
    cudaFuncSetAttribute(mma_gemm_h<0>, cudaFuncAttributeMaxDynamicSharedMemorySize, gemm_smem);
    cudaFuncSetAttribute(mma_gemm_h<2>, cudaFuncAttributeMaxDynamicSharedMemorySize, gemm_smem);
    cudaFuncSetAttribute(mma_gemm_h<3>, cudaFuncAttributeMaxDynamicSharedMemorySize, gemm_smem);
    cudaFuncSetAttribute(mma_gemm_h<4>, cudaFuncAttributeMaxDynamicSharedMemorySize, gemm_smem);

    // 0. fused: LN1 + weight conversion
    prep_ln1_kernel<<<LN_BLOCKS + PREP_BLOCKS, 256>>>(
        x, ln1_g, ln1_b, p_xn,
        (const float4*)qkv_w, (const float4*)proj_w,
        (const float4*)fc1_w, (const float4*)fc2_w,
        (__half2*)p_wq, (__half2*)p_wp, (__half2*)p_w1, (__half2*)p_w2);

    // 1. QKV = xn @ qkv_w^T + b  -> half
    mma_gemm_h<0><<<GEMM_GRID, 256, gemm_smem>>>(
        p_xn, p_wq, qkv_b, nullptr, p_qkv, T_TOK, 2304, D_EMB);
    // 2. flash attention -> half ctx
    attn_mma_kernel<<<dim3(N_SEQ / 128, N_BATCH * N_HEAD), 256>>>(p_qkv, p_ctx);
    // 3. x1 = x + ctx @ proj_w^T + proj_b  -> half
    mma_gemm_h<3><<<GEMM_GRID, 256, gemm_smem>>>(
        p_ctx, p_wp, proj_b, x, p_x1, T_TOK, D_EMB, D_EMB);
    // 4. LN2 (half in, half out)
    ln_h_kernel<<<T_TOK / 8, 256>>>(p_x1, ln2_g, ln2_b, p_xn);
    // 5. h = gelu(xn @ fc1_w^T + fc1_b) -> half
    mma_gemm_h<2><<<GEMM_GRID, 256, gemm_smem>>>(
        p_xn, p_w1, fc1_b, nullptr, p_h, T_TOK, D_HID, D_EMB);
    // 6. out = x1 + h @ fc2_w^T + fc2_b  -> fp32
    mma_gemm_h<4><<<GEMM_GRID, 256, gemm_smem>>>(
        p_h, p_w2, fc2_b, p_x1, out, T_TOK, D_EMB, D_HID);
}

// round 15
// speedup vs baseline: 1.0837x; 1.0837x over previous
#include <cuda_runtime.h>
#include <cuda_fp16.h>
#include <math.h>
#include <stdint.h>

#define T_TOK   16384
#define D_EMB   768
#define D_HID   3072
#define N_HEAD  12
#define HD      64
#define N_SEQ   1024
#define N_BATCH 16

// ---------------- scratch (device globals: allocation-free) ----------------
__device__ __half g_xn [T_TOK * D_EMB];
__device__ __half g_qkv[T_TOK * 3 * D_EMB];
__device__ __half g_ctx[T_TOK * D_EMB];
__device__ __half g_x1 [T_TOK * D_EMB];
__device__ __half g_h  [T_TOK * D_HID];
__device__ __half g_wq[3 * D_EMB * D_EMB];
__device__ __half g_wp[D_EMB * D_EMB];
__device__ __half g_w1[D_HID * D_EMB];
__device__ __half g_w2[D_EMB * D_HID];

// ---------------- helpers ----------------
__device__ __forceinline__ uint32_t s2u(const void* p) {
    uint32_t a;
    asm("{ .reg .u64 t; cvta.to.shared.u64 t, %1; cvt.u32.u64 %0, t; }" : "=r"(a) : "l"(p));
    return a;
}
__device__ __forceinline__ void cp_async16(uint32_t dst, const void* src) {
    asm volatile("cp.async.cg.shared.global [%0], [%1], 16;" :: "r"(dst), "l"(src) : "memory");
}
#define CP_COMMIT() asm volatile("cp.async.commit_group;" ::: "memory")
#define CP_WAIT(n)  asm volatile("cp.async.wait_group %0;" :: "n"(n) : "memory")

__device__ __forceinline__ uint32_t lds32(uint32_t addr) {
    uint32_t v;
    asm volatile("ld.shared.b32 %0, [%1];" : "=r"(v) : "r"(addr));
    return v;
}
__device__ __forceinline__ void ldsm_x4(uint32_t* r, uint32_t addr) {
    asm volatile("ldmatrix.sync.aligned.m8n8.x4.shared.b16 {%0,%1,%2,%3}, [%4];"
                 : "=r"(r[0]), "=r"(r[1]), "=r"(r[2]), "=r"(r[3]) : "r"(addr));
}
__device__ __forceinline__ void ldsm_x4_t(uint32_t* r, uint32_t addr) {
    asm volatile("ldmatrix.sync.aligned.m8n8.x4.trans.shared.b16 {%0,%1,%2,%3}, [%4];"
                 : "=r"(r[0]), "=r"(r[1]), "=r"(r[2]), "=r"(r[3]) : "r"(addr));
}

// D += A * B  (m16n8k16 fp16, fp32 accum)
__device__ __forceinline__ void mma_f16(float* d, const uint32_t* a, const uint32_t* b) {
    asm volatile(
        "mma.sync.aligned.m16n8k16.row.col.f32.f16.f16.f32 "
        "{%0,%1,%2,%3}, {%4,%5,%6,%7}, {%8,%9}, {%0,%1,%2,%3};"
        : "+f"(d[0]), "+f"(d[1]), "+f"(d[2]), "+f"(d[3])
        : "r"(a[0]), "r"(a[1]), "r"(a[2]), "r"(a[3]), "r"(b[0]), "r"(b[1]));
}
__device__ __forceinline__ uint32_t h2u(float a, float b) {
    __half2 h = __floats2half2_rn(a, b);
    return *(uint32_t*)&h;
}
__device__ __forceinline__ uint32_t ex2_h2(uint32_t x) {
    uint32_t y;
    asm("ex2.approx.f16x2 %0, %1;" : "=r"(y) : "r"(x));
    return y;
}

// ---------------- fused prep: LN1 (warp/row) + weight conversion -----------
#define LN_BLOCKS (T_TOK / 8)
#define WQ4 442368
#define WP4 147456
#define W14 589824
#define W24 589824
#define PREP_BLOCKS ((WQ4 + WP4 + W14 + W24) / 256)
__global__ __launch_bounds__(256) void prep_ln1_kernel(
    const float* __restrict__ x, const float* __restrict__ lg,
    const float* __restrict__ lb, __half* __restrict__ xn,
    const float4* __restrict__ wq, const float4* __restrict__ wp,
    const float4* __restrict__ w1, const float4* __restrict__ w2,
    __half2* __restrict__ oq, __half2* __restrict__ op,
    __half2* __restrict__ o1, __half2* __restrict__ o2)
{
    const int tid = threadIdx.x;
    if (blockIdx.x < LN_BLOCKS) {
        const int row = blockIdx.x * 8 + (tid >> 5);
        const int lane = tid & 31;
        const float4* xr = (const float4*)(x + (size_t)row * D_EMB);
        float4 v[6];
        float s = 0.f, q = 0.f;
        #pragma unroll
        for (int u = 0; u < 6; u++) {
            v[u] = xr[lane + u * 32];
            s += v[u].x + v[u].y + v[u].z + v[u].w;
            q += v[u].x * v[u].x + v[u].y * v[u].y + v[u].z * v[u].z + v[u].w * v[u].w;
        }
        #pragma unroll
        for (int o = 16; o > 0; o >>= 1) {
            s += __shfl_xor_sync(0xffffffffu, s, o);
            q += __shfl_xor_sync(0xffffffffu, q, o);
        }
        const float mu = s * (1.0f / D_EMB);
        const float rstd = rsqrtf(q * (1.0f / D_EMB) - mu * mu + 1e-6f);
        const float4* gr = (const float4*)lg;
        const float4* br = (const float4*)lb;
        uint2* orow = (uint2*)(xn + (size_t)row * D_EMB);
        #pragma unroll
        for (int u = 0; u < 6; u++) {
            const int c4 = lane + u * 32;
            float4 g4 = gr[c4], b4 = br[c4];
            float y0 = (v[u].x - mu) * rstd * g4.x + b4.x;
            float y1 = (v[u].y - mu) * rstd * g4.y + b4.y;
            float y2 = (v[u].z - mu) * rstd * g4.z + b4.z;
            float y3 = (v[u].w - mu) * rstd * g4.w + b4.w;
            orow[c4] = make_uint2(h2u(y0, y1), h2u(y2, y3));
        }
        return;
    }
    int i = (blockIdx.x - LN_BLOCKS) * 256 + tid;
    const float4* src; __half2* dst; int r;
    if (i < WQ4) { src = wq; dst = oq; r = i; }
    else if (i < WQ4 + WP4) { src = wp; dst = op; r = i - WQ4; }
    else if (i < WQ4 + WP4 + W14) { src = w1; dst = o1; r = i - WQ4 - WP4; }
    else { src = w2; dst = o2; r = i - WQ4 - WP4 - W14; }
    float4 v = src[r];
    dst[2 * r]     = __floats2half2_rn(v.x, v.y);
    dst[2 * r + 1] = __floats2half2_rn(v.z, v.w);
}

// ---------------- LN2: warp per row, fp16 in, fp16 out ---------------------
__global__ __launch_bounds__(256) void ln_h_kernel(
    const __half* __restrict__ x, const float* __restrict__ lg,
    const float* __restrict__ lb, __half* __restrict__ out)
{
    const int row = blockIdx.x * 8 + (threadIdx.x >> 5);
    const int lane = threadIdx.x & 31;
    const uint4* xr = (const uint4*)(x + (size_t)row * D_EMB);
    uint4 raw[3];
    float vals[3][8];
    float s = 0.f, q = 0.f;
    #pragma unroll
    for (int u = 0; u < 3; u++) {
        raw[u] = xr[lane + u * 32];
        const uint32_t* w = (const uint32_t*)&raw[u];
        #pragma unroll
        for (int p = 0; p < 4; p++) {
            float2 f = __half22float2(*(const __half2*)&w[p]);
            vals[u][2 * p] = f.x; vals[u][2 * p + 1] = f.y;
            s += f.x + f.y;
            q += f.x * f.x + f.y * f.y;
        }
    }
    #pragma unroll
    for (int o = 16; o > 0; o >>= 1) {
        s += __shfl_xor_sync(0xffffffffu, s, o);
        q += __shfl_xor_sync(0xffffffffu, q, o);
    }
    const float mu = s * (1.0f / D_EMB);
    const float rstd = rsqrtf(q * (1.0f / D_EMB) - mu * mu + 1e-6f);
    uint4* orow = (uint4*)(out + (size_t)row * D_EMB);
    const float4* gr = (const float4*)lg;
    const float4* br = (const float4*)lb;
    #pragma unroll
    for (int u = 0; u < 3; u++) {
        const int c8 = lane + u * 32;
        float4 g0 = gr[2 * c8], g1 = gr[2 * c8 + 1];
        float4 b0 = br[2 * c8], b1 = br[2 * c8 + 1];
        uint4 o4;
        o4.x = h2u((vals[u][0] - mu) * rstd * g0.x + b0.x, (vals[u][1] - mu) * rstd * g0.y + b0.y);
        o4.y = h2u((vals[u][2] - mu) * rstd * g0.z + b0.z, (vals[u][3] - mu) * rstd * g0.w + b0.w);
        o4.z = h2u((vals[u][4] - mu) * rstd * g1.x + b1.x, (vals[u][5] - mu) * rstd * g1.y + b1.y);
        o4.w = h2u((vals[u][6] - mu) * rstd * g1.z + b1.z, (vals[u][7] - mu) * rstd * g1.w + b1.w);
        orow[c8] = o4;
    }
}

// ---------------- fp16 mma GEMM (R13 config: 128x128x64, 2-stage, 2 CTA/SM) -
// MODE 0: +bias -> half      MODE 2: gelu(+bias) -> half
// MODE 3: +bias + f32 res -> half     MODE 4: +bias + half res -> f32
#define TILE_BYTES  16384u
#define STAGE_BYTES 32768u
template <int MODE>
__global__ __launch_bounds__(256, 2) void mma_gemm_h(
    const __half* __restrict__ A, const __half* __restrict__ B,
    const float* __restrict__ bias, const void* __restrict__ res,
    void* __restrict__ Cout, int M, int N, int K)
{
    extern __shared__ char smc[];
    const uint32_t sbase = s2u(smc);
    const int tid = threadIdx.x, wid = tid >> 5, lane = tid & 31;
    const int g = lane >> 2, t = lane & 3;
    const int wm = wid >> 2, wn = wid & 3;
    const int m0 = blockIdx.y * 128, n0 = blockIdx.x * 128;
    const int NC = K >> 6;

    const __half* Agb = A + (size_t)m0 * K;
    const __half* Bgb = B + (size_t)n0 * K;

    float acc[4][4][4];
    #pragma unroll
    for (int i = 0; i < 4; i++)
        #pragma unroll
        for (int j = 0; j < 4; j++)
            #pragma unroll
            for (int q = 0; q < 4; q++) acc[i][j][q] = 0.f;

    const uint32_t lx = (uint32_t)(lane & 7);
    uint32_t aRow[4];
    #pragma unroll
    for (int i = 0; i < 4; i++)
        aRow[i] = (uint32_t)((wm * 64 + i * 16 + ((lane >> 3) & 1) * 8 + (lane & 7)) * 128);
    uint32_t coA[4], coB[4];
    #pragma unroll
    for (int ks = 0; ks < 4; ks++) {
        coA[ks] = (((uint32_t)(2 * ks) + (uint32_t)(lane >> 4)) ^ lx) << 4;
        coB[ks] = (((uint32_t)(2 * ks) + (uint32_t)((lane >> 3) & 1)) ^ lx) << 4;
    }
    uint32_t bRow[2];
    #pragma unroll
    for (int p = 0; p < 2; p++)
        bRow[p] = (uint32_t)((wn * 32 + 16 * p + (lane >> 4) * 8 + (lane & 7)) * 128);

    auto load_tile = [&](int kc, int s) {
        uint32_t sa = sbase + (uint32_t)s * STAGE_BYTES;
        uint32_t sb = sa + TILE_BYTES;
        const __half* Ap = Agb + (size_t)kc * 64;
        const __half* Bp = Bgb + (size_t)kc * 64;
        #pragma unroll
        for (int q = 0; q < 4; q++) {
            int it = tid + q * 256;
            int r = it >> 3, c = it & 7;
            uint32_t off = (uint32_t)(r * 128) + (((uint32_t)c ^ (uint32_t)(r & 7)) << 4);
            cp_async16(sa + off, Ap + (size_t)r * K + c * 8);
            cp_async16(sb + off, Bp + (size_t)r * K + c * 8);
        }
        CP_COMMIT();
    };

    load_tile(0, 0);

    for (int c = 0; c < NC; c++) {
        const int cur = c & 1;
        CP_WAIT(0);
        __syncthreads();
        if (c + 1 < NC) load_tile(c + 1, cur ^ 1);

        const uint32_t ab = sbase + (uint32_t)cur * STAGE_BYTES;
        const uint32_t bb = ab + TILE_BYTES;

        #pragma unroll
        for (int ks = 0; ks < 4; ks++) {
            uint32_t afr[4][4];
            #pragma unroll
            for (int i = 0; i < 4; i++)
                ldsm_x4(afr[i], ab + aRow[i] + coA[ks]);
            uint32_t bq[2][4];
            ldsm_x4(bq[0], bb + bRow[0] + coB[ks]);
            ldsm_x4(bq[1], bb + bRow[1] + coB[ks]);
            #pragma unroll
            for (int i = 0; i < 4; i++) {
                #pragma unroll
                for (int j = 0; j < 4; j++)
                    mma_f16(acc[i][j], afr[i], &bq[j >> 1][(j & 1) * 2]);
            }
        }
    }

    // epilogue
    #pragma unroll
    for (int i = 0; i < 4; i++) {
        const int r0 = m0 + wm * 64 + i * 16 + g;
        #pragma unroll
        for (int j = 0; j < 4; j++) {
            const int cc = n0 + wn * 32 + j * 8 + 2 * t;
            float2 bv = *(const float2*)(bias + cc);
            float v00 = acc[i][j][0] + bv.x, v01 = acc[i][j][1] + bv.y;
            float v10 = acc[i][j][2] + bv.x, v11 = acc[i][j][3] + bv.y;
            if (MODE == 3) {
                const float* rf = (const float*)res;
                float2 r0v = *(const float2*)(rf + (size_t)r0 * N + cc);
                float2 r1v = *(const float2*)(rf + (size_t)(r0 + 8) * N + cc);
                v00 += r0v.x; v01 += r0v.y; v10 += r1v.x; v11 += r1v.y;
            }
            if (MODE == 4) {
                const __half* rh = (const __half*)res;
                float2 r0v = __half22float2(*(const __half2*)(rh + (size_t)r0 * N + cc));
                float2 r1v = __half22float2(*(const __half2*)(rh + (size_t)(r0 + 8) * N + cc));
                v00 += r0v.x; v01 += r0v.y; v10 += r1v.x; v11 += r1v.y;
            }
            if (MODE == 2) {
                v00 = 0.5f * v00 * (1.0f + erff(v00 * 0.70710678118654752f));
                v01 = 0.5f * v01 * (1.0f + erff(v01 * 0.70710678118654752f));
                v10 = 0.5f * v10 * (1.0f + erff(v10 * 0.70710678118654752f));
                v11 = 0.5f * v11 * (1.0f + erff(v11 * 0.70710678118654752f));
            }
            if (MODE == 4) {
                float* Cf = (float*)Cout;
                *(float2*)(Cf + (size_t)r0 * N + cc)       = make_float2(v00, v01);
                *(float2*)(Cf + (size_t)(r0 + 8) * N + cc) = make_float2(v10, v11);
            } else {
                __half* Ch = (__half*)Cout;
                *(__half2*)(Ch + (size_t)r0 * N + cc)       = __floats2half2_rn(v00, v01);
                *(__half2*)(Ch + (size_t)(r0 + 8) * N + cc) = __floats2half2_rn(v10, v11);
            }
        }
    }
}

// ---------------- Flash attention: fp16 ex2 softmax ------------------------
__global__ __launch_bounds__(256) void attn_mma_kernel(
    const __half* __restrict__ qkv, __half* __restrict__ ctx)
{
    __shared__ __align__(16) char sQ[16384];
    __shared__ __align__(16) char sK[2][8192];
    __shared__ __align__(16) char sV[2][8192];

    const int tid = threadIdx.x, wid = tid >> 5, lane = tid & 31;
    const int g = lane >> 2, t = lane & 3;
    const int bh = blockIdx.y, b = bh / N_HEAD, h = bh % N_HEAD;
    const int q0 = blockIdx.x * 128;
    const size_t tok_base = (size_t)b * N_SEQ;
    const int hoff = h * HD;
    const uint32_t uQ = s2u(sQ);

    #pragma unroll
    for (int qi = 0; qi < 4; qi++) {
        int it = tid + qi * 256, r = it >> 3, c = it & 7;
        cp_async16(uQ + (uint32_t)(r * 128 + ((c ^ (r & 7)) * 16)),
                   qkv + (tok_base + q0 + r) * 2304 + hoff + c * 8);
    }
    {
        uint32_t uK0 = s2u(sK[0]), uV0 = s2u(sV[0]);
        #pragma unroll
        for (int qi = 0; qi < 2; qi++) {
            int it = tid + qi * 256, r = it >> 3, c = it & 7;
            uint32_t off = (uint32_t)(r * 128 + ((c ^ (r & 7)) * 16));
            cp_async16(uK0 + off, qkv + (tok_base + r) * 2304 + D_EMB + hoff + c * 8);
            cp_async16(uV0 + off, qkv + (tok_base + r) * 2304 + 2 * D_EMB + hoff + c * 8);
        }
    }
    CP_COMMIT();
    CP_WAIT(0);
    __syncthreads();

    // Q fragments pre-scaled by Hd^-0.5 * log2(e)
    uint32_t qf[4][4];
    {
        const int rq = wid * 16 + g;
        const __half2 s8 = __floats2half2_rn(0.18033688f, 0.18033688f);
        #pragma unroll
        for (int ks = 0; ks < 4; ks++) {
            uint32_t ca = (uint32_t)(((2 * ks) ^ (rq & 7)) * 16 + t * 4);
            uint32_t cb = (uint32_t)(((2 * ks + 1) ^ (rq & 7)) * 16 + t * 4);
            qf[ks][0] = lds32(uQ + rq * 128 + ca);
            qf[ks][1] = lds32(uQ + (rq + 8) * 128 + ca);
            qf[ks][2] = lds32(uQ + rq * 128 + cb);
            qf[ks][3] = lds32(uQ + (rq + 8) * 128 + cb);
            #pragma unroll
            for (int u = 0; u < 4; u++) {
                __half2 hv = *(__half2*)&qf[ks][u];
                hv = __hmul2(hv, s8);
                qf[ks][u] = *(uint32_t*)&hv;
            }
        }
    }

    const uint32_t lx = (uint32_t)(lane & 7);
    uint32_t kRow[4], coB[4];
    #pragma unroll
    for (int p = 0; p < 4; p++)
        kRow[p] = (uint32_t)((16 * p + (lane >> 4) * 8 + (lane & 7)) * 128);
    #pragma unroll
    for (int ks = 0; ks < 4; ks++)
        coB[ks] = (((uint32_t)(2 * ks) + (uint32_t)((lane >> 3) & 1)) ^ lx) << 4;
    const uint32_t vRow = (uint32_t)(((lane & 7) + ((lane >> 3) & 1) * 8) * 128);
    uint32_t coV[4];
    #pragma unroll
    for (int jp = 0; jp < 4; jp++)
        coV[jp] = (((uint32_t)(2 * jp) + (uint32_t)(lane >> 4)) ^ lx) << 4;

    float m_g = -1e30f, m_g8 = -1e30f, l_g = 0.f, l_g8 = 0.f;
    float of[8][4];
    #pragma unroll
    for (int j = 0; j < 8; j++)
        #pragma unroll
        for (int q = 0; q < 4; q++) of[j][q] = 0.f;

    for (int kt = 0; kt < N_SEQ / 64; kt++) {
        CP_WAIT(0);
        __syncthreads();

        if (kt + 1 < N_SEQ / 64) {
            uint32_t uKn = s2u(sK[(kt + 1) & 1]), uVn = s2u(sV[(kt + 1) & 1]);
            #pragma unroll
            for (int qi = 0; qi < 2; qi++) {
                int it = tid + qi * 256, r = it >> 3, c = it & 7;
                uint32_t off = (uint32_t)(r * 128 + ((c ^ (r & 7)) * 16));
                cp_async16(uKn + off, qkv + (tok_base + (kt + 1) * 64 + r) * 2304 + D_EMB + hoff + c * 8);
                cp_async16(uVn + off, qkv + (tok_base + (kt + 1) * 64 + r) * 2304 + 2 * D_EMB + hoff + c * 8);
            }
            CP_COMMIT();
        }

        // S = Q K^T  (base-2 logits)
        const uint32_t uKb = s2u(sK[kt & 1]);
        float sf[8][4];
        #pragma unroll
        for (int j = 0; j < 8; j++) {
            sf[j][0] = 0.f; sf[j][1] = 0.f; sf[j][2] = 0.f; sf[j][3] = 0.f;
        }
        #pragma unroll
        for (int ks = 0; ks < 4; ks++) {
            uint32_t kq[4][4];
            #pragma unroll
            for (int p = 0; p < 4; p++)
                ldsm_x4(kq[p], uKb + kRow[p] + coB[ks]);
            #pragma unroll
            for (int j = 0; j < 8; j++)
                mma_f16(sf[j], qf[ks], &kq[j >> 1][(j & 1) * 2]);
        }

        // online softmax: row max
        float mg = m_g, mg8 = m_g8;
        #pragma unroll
        for (int j = 0; j < 8; j++) {
            mg  = fmaxf(mg,  fmaxf(sf[j][0], sf[j][1]));
            mg8 = fmaxf(mg8, fmaxf(sf[j][2], sf[j][3]));
        }
        mg  = fmaxf(mg,  __shfl_xor_sync(0xffffffffu, mg, 1));
        mg  = fmaxf(mg,  __shfl_xor_sync(0xffffffffu, mg, 2));
        mg8 = fmaxf(mg8, __shfl_xor_sync(0xffffffffu, mg8, 1));
        mg8 = fmaxf(mg8, __shfl_xor_sync(0xffffffffu, mg8, 2));
        const float alpha_g = exp2f(m_g - mg), alpha_g8 = exp2f(m_g8 - mg8);
        m_g = mg; m_g8 = mg8;

        // p = ex2(s - m) computed directly in fp16x2 (these ARE the P fragments);
        // l accumulated in fp32 from the SAME fp16 values (num/denom consistent)
        uint32_t pf[4][4];
        float sl_g = 0.f, sl_g8 = 0.f;
        #pragma unroll
        for (int j = 0; j < 8; j++) {
            uint32_t e0 = ex2_h2(h2u(sf[j][0] - mg,  sf[j][1] - mg));
            uint32_t e1 = ex2_h2(h2u(sf[j][2] - mg8, sf[j][3] - mg8));
            pf[j >> 1][(j & 1) * 2]     = e0;
            pf[j >> 1][(j & 1) * 2 + 1] = e1;
            float2 f0 = __half22float2(*(__half2*)&e0);
            float2 f1 = __half22float2(*(__half2*)&e1);
            sl_g  += f0.x + f0.y;
            sl_g8 += f1.x + f1.y;
        }
        sl_g  += __shfl_xor_sync(0xffffffffu, sl_g, 1);
        sl_g  += __shfl_xor_sync(0xffffffffu, sl_g, 2);
        sl_g8 += __shfl_xor_sync(0xffffffffu, sl_g8, 1);
        sl_g8 += __shfl_xor_sync(0xffffffffu, sl_g8, 2);
        l_g  = l_g  * alpha_g  + sl_g;
        l_g8 = l_g8 * alpha_g8 + sl_g8;

        // O = O*alpha + P @ V
        #pragma unroll
        for (int jd = 0; jd < 8; jd++) {
            of[jd][0] *= alpha_g;  of[jd][1] *= alpha_g;
            of[jd][2] *= alpha_g8; of[jd][3] *= alpha_g8;
        }
        const uint32_t uVb = s2u(sV[kt & 1]);
        #pragma unroll
        for (int kp = 0; kp < 4; kp++) {
            uint32_t vqf[4][4];
            #pragma unroll
            for (int jp = 0; jp < 4; jp++)
                ldsm_x4_t(vqf[jp], uVb + (uint32_t)(kp * 2048) + vRow + coV[jp]);
            #pragma unroll
            for (int jd = 0; jd < 8; jd++)
                mma_f16(of[jd], pf[kp], &vqf[jd >> 1][(jd & 1) * 2]);
        }
    }

    const float il_g = 1.0f / l_g, il_g8 = 1.0f / l_g8;
    const int rq = wid * 16 + g;
    #pragma unroll
    for (int jd = 0; jd < 8; jd++) {
        const int col = hoff + 8 * jd + 2 * t;
        *(__half2*)(ctx + (tok_base + q0 + rq) * D_EMB + col) =
            __floats2half2_rn(of[jd][0] * il_g, of[jd][1] * il_g);
        *(__half2*)(ctx + (tok_base + q0 + rq + 8) * D_EMB + col) =
            __floats2half2_rn(of[jd][2] * il_g8, of[jd][3] * il_g8);
    }
}

// ---------------- host launcher ----------------
extern "C" void kernel_launch(void* const* d_in, const int* in_sizes, int n_in,
                              void* d_out, int out_size)
{
    const float* x      = (const float*)d_in[0];
    const float* ln1_g  = (const float*)d_in[1];
    const float* ln1_b  = (const float*)d_in[2];
    const float* qkv_w  = (const float*)d_in[3];
    const float* qkv_b  = (const float*)d_in[4];
    const float* proj_w = (const float*)d_in[5];
    const float* proj_b = (const float*)d_in[6];
    const float* ln2_g  = (const float*)d_in[7];
    const float* ln2_b  = (const float*)d_in[8];
    const float* fc1_w  = (const float*)d_in[9];
    const float* fc1_b  = (const float*)d_in[10];
    const float* fc2_w  = (const float*)d_in[11];
    const float* fc2_b  = (const float*)d_in[12];
    float* out = (float*)d_out;

    __half *p_xn, *p_qkv, *p_ctx, *p_x1, *p_h, *p_wq, *p_wp, *p_w1, *p_w2;
    cudaGetSymbolAddress((void**)&p_xn,  g_xn);
    cudaGetSymbolAddress((void**)&p_qkv, g_qkv);
    cudaGetSymbolAddress((void**)&p_ctx, g_ctx);
    cudaGetSymbolAddress((void**)&p_x1,  g_x1);
    cudaGetSymbolAddress((void**)&p_h,   g_h);
    cudaGetSymbolAddress((void**)&p_wq,  g_wq);
    cudaGetSymbolAddress((void**)&p_wp,  g_wp);
    cudaGetSymbolAddress((void**)&p_w1,  g_w1);
    cudaGetSymbolAddress((void**)&p_w2,  g_w2);

    const int gemm_smem = 2 * (int)STAGE_BYTES;   // 65536 B
    cudaFuncSetAttribute(mma_gemm_h<0>, cudaFuncAttributeMaxDynamicSharedMemorySize, gemm_smem);
    cudaFuncSetAttribute(mma_gemm_h<2>, cudaFuncAttributeMaxDynamicSharedMemorySize, gemm_smem);
    cudaFuncSetAttribute(mma_gemm_h<3>, cudaFuncAttributeMaxDynamicSharedMemorySize, gemm_smem);
    cudaFuncSetAttribute(mma_gemm_h<4>, cudaFuncAttributeMaxDynamicSharedMemorySize, gemm_smem);

    // 0. fused: LN1 + weight conversion
    prep_ln1_kernel<<<LN_BLOCKS + PREP_BLOCKS, 256>>>(
        x, ln1_g, ln1_b, p_xn,
        (const float4*)qkv_w, (const float4*)proj_w,
        (const float4*)fc1_w, (const float4*)fc2_w,
        (__half2*)p_wq, (__half2*)p_wp, (__half2*)p_w1, (__half2*)p_w2);

    // 1. QKV = xn @ qkv_w^T + b  -> half
    mma_gemm_h<0><<<dim3(2304 / 128, T_TOK / 128), 256, gemm_smem>>>(
        p_xn, p_wq, qkv_b, nullptr, p_qkv, T_TOK, 2304, D_EMB);
    // 2. flash attention -> half ctx
    attn_mma_kernel<<<dim3(N_SEQ / 128, N_BATCH * N_HEAD), 256>>>(p_qkv, p_ctx);
    // 3. x1 = x + ctx @ proj_w^T + proj_b  -> half
    mma_gemm_h<3><<<dim3(D_EMB / 128, T_TOK / 128), 256, gemm_smem>>>(
        p_ctx, p_wp, proj_b, x, p_x1, T_TOK, D_EMB, D_EMB);
    // 4. LN2 (half in, half out)
    ln_h_kernel<<<T_TOK / 8, 256>>>(p_x1, ln2_g, ln2_b, p_xn);
    // 5. h = gelu(xn @ fc1_w^T + fc1_b) -> half
    mma_gemm_h<2><<<dim3(D_HID / 128, T_TOK / 128), 256, gemm_smem>>>(
        p_xn, p_w1, fc1_b, nullptr, p_h, T_TOK, D_HID, D_EMB);
    // 6. out = x1 + h @ fc2_w^T + fc2_b  -> fp32
    mma_gemm_h<4><<<dim3(D_EMB / 128, T_TOK / 128), 256, gemm_smem>>>(
        p_h, p_w2, fc2_b, p_x1, out, T_TOK, D_EMB, D_HID);
}

// round 16
// speedup vs baseline: 1.0889x; 1.0048x over previous
#include <cuda_runtime.h>
#include <cuda_fp16.h>
#include <math.h>
#include <stdint.h>

#define T_TOK   16384
#define D_EMB   768
#define D_HID   3072
#define N_HEAD  12
#define HD      64
#define N_SEQ   1024
#define N_BATCH 16

// ---------------- scratch (device globals: allocation-free) ----------------
__device__ __half g_xn [T_TOK * D_EMB];
__device__ __half g_qkv[T_TOK * 3 * D_EMB];
__device__ __half g_ctx[T_TOK * D_EMB];
__device__ __half g_x1 [T_TOK * D_EMB];
__device__ __half g_h  [T_TOK * D_HID];
__device__ __half g_wq[3 * D_EMB * D_EMB];
__device__ __half g_wp[D_EMB * D_EMB];
__device__ __half g_w1[D_HID * D_EMB];
__device__ __half g_w2[D_EMB * D_HID];

// ---------------- helpers ----------------
__device__ __forceinline__ uint32_t s2u(const void* p) {
    uint32_t a;
    asm("{ .reg .u64 t; cvta.to.shared.u64 t, %1; cvt.u32.u64 %0, t; }" : "=r"(a) : "l"(p));
    return a;
}
__device__ __forceinline__ void cp_async16(uint32_t dst, const void* src) {
    asm volatile("cp.async.cg.shared.global [%0], [%1], 16;" :: "r"(dst), "l"(src) : "memory");
}
#define CP_COMMIT() asm volatile("cp.async.commit_group;" ::: "memory")
#define CP_WAIT(n)  asm volatile("cp.async.wait_group %0;" :: "n"(n) : "memory")

__device__ __forceinline__ uint32_t lds32(uint32_t addr) {
    uint32_t v;
    asm volatile("ld.shared.b32 %0, [%1];" : "=r"(v) : "r"(addr));
    return v;
}
__device__ __forceinline__ void ldsm_x4(uint32_t* r, uint32_t addr) {
    asm volatile("ldmatrix.sync.aligned.m8n8.x4.shared.b16 {%0,%1,%2,%3}, [%4];"
                 : "=r"(r[0]), "=r"(r[1]), "=r"(r[2]), "=r"(r[3]) : "r"(addr));
}
__device__ __forceinline__ void ldsm_x4_t(uint32_t* r, uint32_t addr) {
    asm volatile("ldmatrix.sync.aligned.m8n8.x4.trans.shared.b16 {%0,%1,%2,%3}, [%4];"
                 : "=r"(r[0]), "=r"(r[1]), "=r"(r[2]), "=r"(r[3]) : "r"(addr));
}

// D += A * B  (m16n8k16 fp16, fp32 accum)
__device__ __forceinline__ void mma_f16(float* d, const uint32_t* a, const uint32_t* b) {
    asm volatile(
        "mma.sync.aligned.m16n8k16.row.col.f32.f16.f16.f32 "
        "{%0,%1,%2,%3}, {%4,%5,%6,%7}, {%8,%9}, {%0,%1,%2,%3};"
        : "+f"(d[0]), "+f"(d[1]), "+f"(d[2]), "+f"(d[3])
        : "r"(a[0]), "r"(a[1]), "r"(a[2]), "r"(a[3]), "r"(b[0]), "r"(b[1]));
}
__device__ __forceinline__ uint32_t h2u(float a, float b) {
    __half2 h = __floats2half2_rn(a, b);
    return *(uint32_t*)&h;
}
__device__ __forceinline__ uint32_t ex2_h2(uint32_t x) {
    uint32_t y;
    asm("ex2.approx.f16x2 %0, %1;" : "=r"(y) : "r"(x));
    return y;
}

// ---------------- fused prep: LN1 (warp/row) + weight conversion -----------
#define LN_BLOCKS (T_TOK / 8)
#define WQ4 442368
#define WP4 147456
#define W14 589824
#define W24 589824
#define PREP_BLOCKS ((WQ4 + WP4 + W14 + W24) / 256)
__global__ __launch_bounds__(256) void prep_ln1_kernel(
    const float* __restrict__ x, const float* __restrict__ lg,
    const float* __restrict__ lb, __half* __restrict__ xn,
    const float4* __restrict__ wq, const float4* __restrict__ wp,
    const float4* __restrict__ w1, const float4* __restrict__ w2,
    __half2* __restrict__ oq, __half2* __restrict__ op,
    __half2* __restrict__ o1, __half2* __restrict__ o2)
{
    const int tid = threadIdx.x;
    if (blockIdx.x < LN_BLOCKS) {
        const int row = blockIdx.x * 8 + (tid >> 5);
        const int lane = tid & 31;
        const float4* xr = (const float4*)(x + (size_t)row * D_EMB);
        float4 v[6];
        float s = 0.f, q = 0.f;
        #pragma unroll
        for (int u = 0; u < 6; u++) {
            v[u] = xr[lane + u * 32];
            s += v[u].x + v[u].y + v[u].z + v[u].w;
            q += v[u].x * v[u].x + v[u].y * v[u].y + v[u].z * v[u].z + v[u].w * v[u].w;
        }
        #pragma unroll
        for (int o = 16; o > 0; o >>= 1) {
            s += __shfl_xor_sync(0xffffffffu, s, o);
            q += __shfl_xor_sync(0xffffffffu, q, o);
        }
        const float mu = s * (1.0f / D_EMB);
        const float rstd = rsqrtf(q * (1.0f / D_EMB) - mu * mu + 1e-6f);
        const float4* gr = (const float4*)lg;
        const float4* br = (const float4*)lb;
        uint2* orow = (uint2*)(xn + (size_t)row * D_EMB);
        #pragma unroll
        for (int u = 0; u < 6; u++) {
            const int c4 = lane + u * 32;
            float4 g4 = gr[c4], b4 = br[c4];
            float y0 = (v[u].x - mu) * rstd * g4.x + b4.x;
            float y1 = (v[u].y - mu) * rstd * g4.y + b4.y;
            float y2 = (v[u].z - mu) * rstd * g4.z + b4.z;
            float y3 = (v[u].w - mu) * rstd * g4.w + b4.w;
            orow[c4] = make_uint2(h2u(y0, y1), h2u(y2, y3));
        }
        return;
    }
    int i = (blockIdx.x - LN_BLOCKS) * 256 + tid;
    const float4* src; __half2* dst; int r;
    if (i < WQ4) { src = wq; dst = oq; r = i; }
    else if (i < WQ4 + WP4) { src = wp; dst = op; r = i - WQ4; }
    else if (i < WQ4 + WP4 + W14) { src = w1; dst = o1; r = i - WQ4 - WP4; }
    else { src = w2; dst = o2; r = i - WQ4 - WP4 - W14; }
    float4 v = src[r];
    dst[2 * r]     = __floats2half2_rn(v.x, v.y);
    dst[2 * r + 1] = __floats2half2_rn(v.z, v.w);
}

// ---------------- LN2: warp per row, fp16 in, fp16 out ---------------------
__global__ __launch_bounds__(256) void ln_h_kernel(
    const __half* __restrict__ x, const float* __restrict__ lg,
    const float* __restrict__ lb, __half* __restrict__ out)
{
    const int row = blockIdx.x * 8 + (threadIdx.x >> 5);
    const int lane = threadIdx.x & 31;
    const uint4* xr = (const uint4*)(x + (size_t)row * D_EMB);
    uint4 raw[3];
    float vals[3][8];
    float s = 0.f, q = 0.f;
    #pragma unroll
    for (int u = 0; u < 3; u++) {
        raw[u] = xr[lane + u * 32];
        const uint32_t* w = (const uint32_t*)&raw[u];
        #pragma unroll
        for (int p = 0; p < 4; p++) {
            float2 f = __half22float2(*(const __half2*)&w[p]);
            vals[u][2 * p] = f.x; vals[u][2 * p + 1] = f.y;
            s += f.x + f.y;
            q += f.x * f.x + f.y * f.y;
        }
    }
    #pragma unroll
    for (int o = 16; o > 0; o >>= 1) {
        s += __shfl_xor_sync(0xffffffffu, s, o);
        q += __shfl_xor_sync(0xffffffffu, q, o);
    }
    const float mu = s * (1.0f / D_EMB);
    const float rstd = rsqrtf(q * (1.0f / D_EMB) - mu * mu + 1e-6f);
    uint4* orow = (uint4*)(out + (size_t)row * D_EMB);
    const float4* gr = (const float4*)lg;
    const float4* br = (const float4*)lb;
    #pragma unroll
    for (int u = 0; u < 3; u++) {
        const int c8 = lane + u * 32;
        float4 g0 = gr[2 * c8], g1 = gr[2 * c8 + 1];
        float4 b0 = br[2 * c8], b1 = br[2 * c8 + 1];
        uint4 o4;
        o4.x = h2u((vals[u][0] - mu) * rstd * g0.x + b0.x, (vals[u][1] - mu) * rstd * g0.y + b0.y);
        o4.y = h2u((vals[u][2] - mu) * rstd * g0.z + b0.z, (vals[u][3] - mu) * rstd * g0.w + b0.w);
        o4.z = h2u((vals[u][4] - mu) * rstd * g1.x + b1.x, (vals[u][5] - mu) * rstd * g1.y + b1.y);
        o4.w = h2u((vals[u][6] - mu) * rstd * g1.z + b1.z, (vals[u][7] - mu) * rstd * g1.w + b1.w);
        orow[c8] = o4;
    }
}

// ---------------- fp16 mma GEMM (R13 config: 128x128x64, 2-stage, 2 CTA/SM) -
// MODE 0: +bias -> half      MODE 2: gelu(+bias) -> half
// MODE 3: +bias + f32 res -> half     MODE 4: +bias + half res -> f32
#define TILE_BYTES  16384u
#define STAGE_BYTES 32768u
template <int MODE>
__global__ __launch_bounds__(256, 2) void mma_gemm_h(
    const __half* __restrict__ A, const __half* __restrict__ B,
    const float* __restrict__ bias, const void* __restrict__ res,
    void* __restrict__ Cout, int M, int N, int K)
{
    extern __shared__ char smc[];
    const uint32_t sbase = s2u(smc);
    const int tid = threadIdx.x, wid = tid >> 5, lane = tid & 31;
    const int g = lane >> 2, t = lane & 3;
    const int wm = wid >> 2, wn = wid & 3;
    const int m0 = blockIdx.y * 128, n0 = blockIdx.x * 128;
    const int NC = K >> 6;

    const __half* Agb = A + (size_t)m0 * K;
    const __half* Bgb = B + (size_t)n0 * K;

    float acc[4][4][4];
    #pragma unroll
    for (int i = 0; i < 4; i++)
        #pragma unroll
        for (int j = 0; j < 4; j++)
            #pragma unroll
            for (int q = 0; q < 4; q++) acc[i][j][q] = 0.f;

    const uint32_t lx = (uint32_t)(lane & 7);
    uint32_t aRow[4];
    #pragma unroll
    for (int i = 0; i < 4; i++)
        aRow[i] = (uint32_t)((wm * 64 + i * 16 + ((lane >> 3) & 1) * 8 + (lane & 7)) * 128);
    uint32_t coA[4], coB[4];
    #pragma unroll
    for (int ks = 0; ks < 4; ks++) {
        coA[ks] = (((uint32_t)(2 * ks) + (uint32_t)(lane >> 4)) ^ lx) << 4;
        coB[ks] = (((uint32_t)(2 * ks) + (uint32_t)((lane >> 3) & 1)) ^ lx) << 4;
    }
    uint32_t bRow[2];
    #pragma unroll
    for (int p = 0; p < 2; p++)
        bRow[p] = (uint32_t)((wn * 32 + 16 * p + (lane >> 4) * 8 + (lane & 7)) * 128);

    auto load_tile = [&](int kc, int s) {
        uint32_t sa = sbase + (uint32_t)s * STAGE_BYTES;
        uint32_t sb = sa + TILE_BYTES;
        const __half* Ap = Agb + (size_t)kc * 64;
        const __half* Bp = Bgb + (size_t)kc * 64;
        #pragma unroll
        for (int q = 0; q < 4; q++) {
            int it = tid + q * 256;
            int r = it >> 3, c = it & 7;
            uint32_t off = (uint32_t)(r * 128) + (((uint32_t)c ^ (uint32_t)(r & 7)) << 4);
            cp_async16(sa + off, Ap + (size_t)r * K + c * 8);
            cp_async16(sb + off, Bp + (size_t)r * K + c * 8);
        }
        CP_COMMIT();
    };

    load_tile(0, 0);

    for (int c = 0; c < NC; c++) {
        const int cur = c & 1;
        CP_WAIT(0);
        __syncthreads();
        if (c + 1 < NC) load_tile(c + 1, cur ^ 1);

        const uint32_t ab = sbase + (uint32_t)cur * STAGE_BYTES;
        const uint32_t bb = ab + TILE_BYTES;

        #pragma unroll
        for (int ks = 0; ks < 4; ks++) {
            uint32_t afr[4][4];
            #pragma unroll
            for (int i = 0; i < 4; i++)
                ldsm_x4(afr[i], ab + aRow[i] + coA[ks]);
            uint32_t bq[2][4];
            ldsm_x4(bq[0], bb + bRow[0] + coB[ks]);
            ldsm_x4(bq[1], bb + bRow[1] + coB[ks]);
            #pragma unroll
            for (int i = 0; i < 4; i++) {
                #pragma unroll
                for (int j = 0; j < 4; j++)
                    mma_f16(acc[i][j], afr[i], &bq[j >> 1][(j & 1) * 2]);
            }
        }
    }

    // epilogue
    #pragma unroll
    for (int i = 0; i < 4; i++) {
        const int r0 = m0 + wm * 64 + i * 16 + g;
        #pragma unroll
        for (int j = 0; j < 4; j++) {
            const int cc = n0 + wn * 32 + j * 8 + 2 * t;
            float2 bv = *(const float2*)(bias + cc);
            float v00 = acc[i][j][0] + bv.x, v01 = acc[i][j][1] + bv.y;
            float v10 = acc[i][j][2] + bv.x, v11 = acc[i][j][3] + bv.y;
            if (MODE == 3) {
                const float* rf = (const float*)res;
                float2 r0v = *(const float2*)(rf + (size_t)r0 * N + cc);
                float2 r1v = *(const float2*)(rf + (size_t)(r0 + 8) * N + cc);
                v00 += r0v.x; v01 += r0v.y; v10 += r1v.x; v11 += r1v.y;
            }
            if (MODE == 4) {
                const __half* rh = (const __half*)res;
                float2 r0v = __half22float2(*(const __half2*)(rh + (size_t)r0 * N + cc));
                float2 r1v = __half22float2(*(const __half2*)(rh + (size_t)(r0 + 8) * N + cc));
                v00 += r0v.x; v01 += r0v.y; v10 += r1v.x; v11 += r1v.y;
            }
            if (MODE == 2) {
                v00 = 0.5f * v00 * (1.0f + erff(v00 * 0.70710678118654752f));
                v01 = 0.5f * v01 * (1.0f + erff(v01 * 0.70710678118654752f));
                v10 = 0.5f * v10 * (1.0f + erff(v10 * 0.70710678118654752f));
                v11 = 0.5f * v11 * (1.0f + erff(v11 * 0.70710678118654752f));
            }
            if (MODE == 4) {
                float* Cf = (float*)Cout;
                *(float2*)(Cf + (size_t)r0 * N + cc)       = make_float2(v00, v01);
                *(float2*)(Cf + (size_t)(r0 + 8) * N + cc) = make_float2(v10, v11);
            } else {
                __half* Ch = (__half*)Cout;
                *(__half2*)(Ch + (size_t)r0 * N + cc)       = __floats2half2_rn(v00, v01);
                *(__half2*)(Ch + (size_t)(r0 + 8) * N + cc) = __floats2half2_rn(v10, v11);
            }
        }
    }
}

// ---------------- Flash attention: 3-deep K/V ring, staged cp.async waits --
// dynamic smem layout: Q[16384] | K[3][8192] | V[3][8192]  = 65536 B
#define ATT_Q_OFF 0u
#define ATT_K_OFF 16384u
#define ATT_V_OFF 40960u
#define ATT_SMEM  65536
__global__ __launch_bounds__(256) void attn_mma_kernel(
    const __half* __restrict__ qkv, __half* __restrict__ ctx)
{
    extern __shared__ char sma[];
    const uint32_t uS = s2u(sma);
    const uint32_t uQ = uS + ATT_Q_OFF;

    const int tid = threadIdx.x, wid = tid >> 5, lane = tid & 31;
    const int g = lane >> 2, t = lane & 3;
    const int bh = blockIdx.y, b = bh / N_HEAD, h = bh % N_HEAD;
    const int q0 = blockIdx.x * 128;
    const size_t tok_base = (size_t)b * N_SEQ;
    const int hoff = h * HD;

    // K/V tile loader (64 keys, 64 dims, XOR-swizzled)
    auto load_kv = [&](int kt, int s) {
        uint32_t uK = uS + ATT_K_OFF + (uint32_t)s * 8192u;
        uint32_t uV = uS + ATT_V_OFF + (uint32_t)s * 8192u;
        #pragma unroll
        for (int qi = 0; qi < 2; qi++) {
            int it = tid + qi * 256, r = it >> 3, c = it & 7;
            uint32_t off = (uint32_t)(r * 128 + ((c ^ (r & 7)) * 16));
            cp_async16(uK + off, qkv + (tok_base + kt * 64 + r) * 2304 + D_EMB + hoff + c * 8);
            cp_async16(uV + off, qkv + (tok_base + kt * 64 + r) * 2304 + 2 * D_EMB + hoff + c * 8);
        }
        CP_COMMIT();
    };

    // prologue: group A = Q + K(0)/V(0);  group B = K(1)/V(1)
    #pragma unroll
    for (int qi = 0; qi < 4; qi++) {
        int it = tid + qi * 256, r = it >> 3, c = it & 7;
        cp_async16(uQ + (uint32_t)(r * 128 + ((c ^ (r & 7)) * 16)),
                   qkv + (tok_base + q0 + r) * 2304 + hoff + c * 8);
    }
    load_kv(0, 0);   // commits group A (Q + KV0)
    load_kv(1, 1);   // commits group B
    CP_WAIT(1);      // group A done (Q, K0, V0 resident); B in flight
    __syncthreads();

    // Q fragments pre-scaled by Hd^-0.5 * log2(e)
    uint32_t qf[4][4];
    {
        const int rq = wid * 16 + g;
        const __half2 s8 = __floats2half2_rn(0.18033688f, 0.18033688f);
        #pragma unroll
        for (int ks = 0; ks < 4; ks++) {
            uint32_t ca = (uint32_t)(((2 * ks) ^ (rq & 7)) * 16 + t * 4);
            uint32_t cb = (uint32_t)(((2 * ks + 1) ^ (rq & 7)) * 16 + t * 4);
            qf[ks][0] = lds32(uQ + rq * 128 + ca);
            qf[ks][1] = lds32(uQ + (rq + 8) * 128 + ca);
            qf[ks][2] = lds32(uQ + rq * 128 + cb);
            qf[ks][3] = lds32(uQ + (rq + 8) * 128 + cb);
            #pragma unroll
            for (int u = 0; u < 4; u++) {
                __half2 hv = *(__half2*)&qf[ks][u];
                hv = __hmul2(hv, s8);
                qf[ks][u] = *(uint32_t*)&hv;
            }
        }
    }

    const uint32_t lx = (uint32_t)(lane & 7);
    uint32_t kRow[4], coB[4];
    #pragma unroll
    for (int p = 0; p < 4; p++)
        kRow[p] = (uint32_t)((16 * p + (lane >> 4) * 8 + (lane & 7)) * 128);
    #pragma unroll
    for (int ks = 0; ks < 4; ks++)
        coB[ks] = (((uint32_t)(2 * ks) + (uint32_t)((lane >> 3) & 1)) ^ lx) << 4;
    const uint32_t vRow = (uint32_t)(((lane & 7) + ((lane >> 3) & 1) * 8) * 128);
    uint32_t coV[4];
    #pragma unroll
    for (int jp = 0; jp < 4; jp++)
        coV[jp] = (((uint32_t)(2 * jp) + (uint32_t)(lane >> 4)) ^ lx) << 4;

    float m_g = -1e30f, m_g8 = -1e30f, l_g = 0.f, l_g8 = 0.f;
    float of[8][4];
    #pragma unroll
    for (int j = 0; j < 8; j++)
        #pragma unroll
        for (int q = 0; q < 4; q++) of[j][q] = 0.f;

    const int NS = N_SEQ / 64;
    for (int kt = 0; kt < NS; kt++) {
        const int s = kt % 3;
        __syncthreads();   // all warps done reading buffer (kt+2)%3 (iter kt-1)

        // prefetch kt+2, then retire exactly group kt
        if (kt + 2 < NS) {
            load_kv(kt + 2, (kt + 2) % 3);
            CP_WAIT(2);    // pending {kt+1, kt+2}; group kt complete
        } else if (kt + 1 < NS) {
            CP_WAIT(1);
        } else {
            CP_WAIT(0);
        }

        // S = Q K^T  (base-2 logits)
        const uint32_t uKb = uS + ATT_K_OFF + (uint32_t)s * 8192u;
        float sf[8][4];
        #pragma unroll
        for (int j = 0; j < 8; j++) {
            sf[j][0] = 0.f; sf[j][1] = 0.f; sf[j][2] = 0.f; sf[j][3] = 0.f;
        }
        #pragma unroll
        for (int ks = 0; ks < 4; ks++) {
            uint32_t kq[4][4];
            #pragma unroll
            for (int p = 0; p < 4; p++)
                ldsm_x4(kq[p], uKb + kRow[p] + coB[ks]);
            #pragma unroll
            for (int j = 0; j < 8; j++)
                mma_f16(sf[j], qf[ks], &kq[j >> 1][(j & 1) * 2]);
        }

        // online softmax: row max
        float mg = m_g, mg8 = m_g8;
        #pragma unroll
        for (int j = 0; j < 8; j++) {
            mg  = fmaxf(mg,  fmaxf(sf[j][0], sf[j][1]));
            mg8 = fmaxf(mg8, fmaxf(sf[j][2], sf[j][3]));
        }
        mg  = fmaxf(mg,  __shfl_xor_sync(0xffffffffu, mg, 1));
        mg  = fmaxf(mg,  __shfl_xor_sync(0xffffffffu, mg, 2));
        mg8 = fmaxf(mg8, __shfl_xor_sync(0xffffffffu, mg8, 1));
        mg8 = fmaxf(mg8, __shfl_xor_sync(0xffffffffu, mg8, 2));
        const float alpha_g = exp2f(m_g - mg), alpha_g8 = exp2f(m_g8 - mg8);
        m_g = mg; m_g8 = mg8;

        // p = ex2(s - m) directly in fp16x2 (these ARE the P fragments)
        uint32_t pf[4][4];
        float sl_g = 0.f, sl_g8 = 0.f;
        #pragma unroll
        for (int j = 0; j < 8; j++) {
            uint32_t e0 = ex2_h2(h2u(sf[j][0] - mg,  sf[j][1] - mg));
            uint32_t e1 = ex2_h2(h2u(sf[j][2] - mg8, sf[j][3] - mg8));
            pf[j >> 1][(j & 1) * 2]     = e0;
            pf[j >> 1][(j & 1) * 2 + 1] = e1;
            float2 f0 = __half22float2(*(__half2*)&e0);
            float2 f1 = __half22float2(*(__half2*)&e1);
            sl_g  += f0.x + f0.y;
            sl_g8 += f1.x + f1.y;
        }
        sl_g  += __shfl_xor_sync(0xffffffffu, sl_g, 1);
        sl_g  += __shfl_xor_sync(0xffffffffu, sl_g, 2);
        sl_g8 += __shfl_xor_sync(0xffffffffu, sl_g8, 1);
        sl_g8 += __shfl_xor_sync(0xffffffffu, sl_g8, 2);
        l_g  = l_g  * alpha_g  + sl_g;
        l_g8 = l_g8 * alpha_g8 + sl_g8;

        // O = O*alpha + P @ V
        #pragma unroll
        for (int jd = 0; jd < 8; jd++) {
            of[jd][0] *= alpha_g;  of[jd][1] *= alpha_g;
            of[jd][2] *= alpha_g8; of[jd][3] *= alpha_g8;
        }
        const uint32_t uVb = uS + ATT_V_OFF + (uint32_t)s * 8192u;
        #pragma unroll
        for (int kp = 0; kp < 4; kp++) {
            uint32_t vqf[4][4];
            #pragma unroll
            for (int jp = 0; jp < 4; jp++)
                ldsm_x4_t(vqf[jp], uVb + (uint32_t)(kp * 2048) + vRow + coV[jp]);
            #pragma unroll
            for (int jd = 0; jd < 8; jd++)
                mma_f16(of[jd], pf[kp], &vqf[jd >> 1][(jd & 1) * 2]);
        }
    }

    const float il_g = 1.0f / l_g, il_g8 = 1.0f / l_g8;
    const int rq = wid * 16 + g;
    #pragma unroll
    for (int jd = 0; jd < 8; jd++) {
        const int col = hoff + 8 * jd + 2 * t;
        *(__half2*)(ctx + (tok_base + q0 + rq) * D_EMB + col) =
            __floats2half2_rn(of[jd][0] * il_g, of[jd][1] * il_g);
        *(__half2*)(ctx + (tok_base + q0 + rq + 8) * D_EMB + col) =
            __floats2half2_rn(of[jd][2] * il_g8, of[jd][3] * il_g8);
    }
}

// ---------------- host launcher ----------------
extern "C" void kernel_launch(void* const* d_in, const int* in_sizes, int n_in,
                              void* d_out, int out_size)
{
    const float* x      = (const float*)d_in[0];
    const float* ln1_g  = (const float*)d_in[1];
    const float* ln1_b  = (const float*)d_in[2];
    const float* qkv_w  = (const float*)d_in[3];
    const float* qkv_b  = (const float*)d_in[4];
    const float* proj_w = (const float*)d_in[5];
    const float* proj_b = (const float*)d_in[6];
    const float* ln2_g  = (const float*)d_in[7];
    const float* ln2_b  = (const float*)d_in[8];
    const float* fc1_w  = (const float*)d_in[9];
    const float* fc1_b  = (const float*)d_in[10];
    const float* fc2_w  = (const float*)d_in[11];
    const float* fc2_b  = (const float*)d_in[12];
    float* out = (float*)d_out;

    __half *p_xn, *p_qkv, *p_ctx, *p_x1, *p_h, *p_wq, *p_wp, *p_w1, *p_w2;
    cudaGetSymbolAddress((void**)&p_xn,  g_xn);
    cudaGetSymbolAddress((void**)&p_qkv, g_qkv);
    cudaGetSymbolAddress((void**)&p_ctx, g_ctx);
    cudaGetSymbolAddress((void**)&p_x1,  g_x1);
    cudaGetSymbolAddress((void**)&p_h,   g_h);
    cudaGetSymbolAddress((void**)&p_wq,  g_wq);
    cudaGetSymbolAddress((void**)&p_wp,  g_wp);
    cudaGetSymbolAddress((void**)&p_w1,  g_w1);
    cudaGetSymbolAddress((void**)&p_w2,  g_w2);

    const int gemm_smem = 2 * (int)STAGE_BYTES;   // 65536 B
    cudaFuncSetAttribute(mma_gemm_h<0>, cudaFuncAttributeMaxDynamicSharedMemorySize, gemm_smem);
    cudaFuncSetAttribute(mma_gemm_h<2>, cudaFuncAttributeMaxDynamicSharedMemorySize, gemm_smem);
    cudaFuncSetAttribute(mma_gemm_h<3>, cudaFuncAttributeMaxDynamicSharedMemorySize, gemm_smem);
    cudaFuncSetAttribute(mma_gemm_h<4>, cudaFuncAttributeMaxDynamicSharedMemorySize, gemm_smem);
    cudaFuncSetAttribute(attn_mma_kernel, cudaFuncAttributeMaxDynamicSharedMemorySize, ATT_SMEM);

    // 0. fused: LN1 + weight conversion
    prep_ln1_kernel<<<LN_BLOCKS + PREP_BLOCKS, 256>>>(
        x, ln1_g, ln1_b, p_xn,
        (const float4*)qkv_w, (const float4*)proj_w,
        (const float4*)fc1_w, (const float4*)fc2_w,
        (__half2*)p_wq, (__half2*)p_wp, (__half2*)p_w1, (__half2*)p_w2);

    // 1. QKV = xn @ qkv_w^T + b  -> half
    mma_gemm_h<0><<<dim3(2304 / 128, T_TOK / 128), 256, gemm_smem>>>(
        p_xn, p_wq, qkv_b, nullptr, p_qkv, T_TOK, 2304, D_EMB);
    // 2. flash attention -> half ctx
    attn_mma_kernel<<<dim3(N_SEQ / 128, N_BATCH * N_HEAD), 256, ATT_SMEM>>>(p_qkv, p_ctx);
    // 3. x1 = x + ctx @ proj_w^T + proj_b  -> half
    mma_gemm_h<3><<<dim3(D_EMB / 128, T_TOK / 128), 256, gemm_smem>>>(
        p_ctx, p_wp, proj_b, x, p_x1, T_TOK, D_EMB, D_EMB);
    // 4. LN2 (half in, half out)
    ln_h_kernel<<<T_TOK / 8, 256>>>(p_x1, ln2_g, ln2_b, p_xn);
    // 5. h = gelu(xn @ fc1_w^T + fc1_b) -> half
    mma_gemm_h<2><<<dim3(D_HID / 128, T_TOK / 128), 256, gemm_smem>>>(
        p_xn, p_w1, fc1_b, nullptr, p_h, T_TOK, D_HID, D_EMB);
    // 6. out = x1 + h @ fc2_w^T + fc2_b  -> fp32
    mma_gemm_h<4><<<dim3(D_EMB / 128, T_TOK / 128), 256, gemm_smem>>>(
        p_h, p_w2, fc2_b, p_x1, out, T_TOK, D_EMB, D_HID);
}